// round 9
// baseline (speedup 1.0000x reference)
#include <cuda_runtime.h>
#include <cuda_fp16.h>
#include <stdint.h>

#define C_CHUNKS 16
#define NCW      2048
#define SUB      64
#define DIM      1024
#define TM       128
#define BT       128            // codewords per B tile
#define NBT      (NCW / BT)     // 16
#define NTHR     512

// smem offsets (bytes); B/A row stride 72 halves = 144B (LDSM conflict-free)
#define SM_A     0              // 128 x 144B = 18432
#define SM_B     18432          // 2 x 18432 = 36864
#define SM_BIAS  55296          // 2 x 128 f32 = 1024
#define SM_XSQ   56320          // 128 f32
#define SM_EPS   56832          // 128 f32 (per-token 2*eps threshold)
#define SM_MAX   57344          // 64 x 128 f32 = 32768
#define SM_TOP   90112          // 3 x 256 f32 = 3072 (t1v/t2v/t1i x [ng][row])
#define SM_TOTAL 93184
// overlays on SM_B after mainloop:
#define SM_WL    SM_B           // worst case 8192 x u32 = 32768
#define SM_BEST  (SM_B + 32768) // 128 x u64
#define SM_WCNT  (SM_B + 33800)

typedef unsigned long long ull;

__device__ float g_cbsq[C_CHUNKS * NCW];
__device__ float g_bias[C_CHUNKS * NCW];
__device__ float g_cmax[C_CHUNKS * SUB];       // per (chunk,k) max |c|
__device__ uint4 g_bimg[C_CHUNKS * NCW * 8];   // fp16 codebook, [row][64] halves

// ---------------------------------------------------------------------------
__device__ __forceinline__ uint32_t smem_u32(const void* p) {
    uint32_t a;
    asm("{ .reg .u64 t; cvta.to.shared.u64 t, %1; cvt.u32.u64 %0, t; }"
        : "=r"(a) : "l"(p));
    return a;
}
__device__ __forceinline__ void ldsm4(uint32_t& r0, uint32_t& r1, uint32_t& r2,
                                      uint32_t& r3, uint32_t a) {
    asm volatile("ldmatrix.sync.aligned.m8n8.x4.shared.b16 {%0,%1,%2,%3}, [%4];"
                 : "=r"(r0), "=r"(r1), "=r"(r2), "=r"(r3) : "r"(a));
}
__device__ __forceinline__ void mma16816(float* d, const uint32_t* a,
                                         uint32_t b0, uint32_t b1) {
    asm volatile(
        "mma.sync.aligned.m16n8k16.row.col.f32.f16.f16.f32 "
        "{%0,%1,%2,%3}, {%4,%5,%6,%7}, {%8,%9}, {%0,%1,%2,%3};"
        : "+f"(d[0]), "+f"(d[1]), "+f"(d[2]), "+f"(d[3])
        : "r"(a[0]), "r"(a[1]), "r"(a[2]), "r"(a[3]), "r"(b0), "r"(b1));
}
__device__ __forceinline__ void cp16(uint32_t dst, const void* src) {
    asm volatile("cp.async.cg.shared.global [%0], [%1], 16;"
                 :: "r"(dst), "l"(src));
}
__device__ __forceinline__ void cp4(uint32_t dst, const void* src) {
    asm volatile("cp.async.ca.shared.global [%0], [%1], 4;"
                 :: "r"(dst), "l"(src));
}
#define CP_COMMIT() asm volatile("cp.async.commit_group;" ::: "memory")
#define CP_WAIT0()  asm volatile("cp.async.wait_group 0;" ::: "memory")

__device__ __forceinline__ uint32_t ord_f32(float f) {
    uint32_t u = __float_as_uint(f);
    return (u & 0x80000000u) ? ~u : (u | 0x80000000u);
}
// top-2 update, select form
__device__ __forceinline__ void upd2(float& t1, int& ti, float& t2,
                                     float v, int n) {
    const bool g = v > t1;
    t2 = g ? t1 : fmaxf(t2, v);
    ti = g ? n : ti;
    t1 = g ? v : t1;
}

// ---------------------------------------------------------------------------
// prep: fp16 codebook image (row-contiguous k) + cbsq + bias
// ---------------------------------------------------------------------------
__global__ void prep_kernel(const float* __restrict__ cb) {
    int n = blockIdx.x * 256 + threadIdx.x;          // 0..32767
    const float4* cp = reinterpret_cast<const float4*>(cb + (size_t)n * SUB);
    uint4 outv[8];
    uint32_t* ow = reinterpret_cast<uint32_t*>(outv);
    float ssq = 0.f;
    #pragma unroll
    for (int q = 0; q < 16; q++) {
        float4 v = cp[q];
        __half2 h0 = __floats2half2_rn(v.x, v.y);
        __half2 h1 = __floats2half2_rn(v.z, v.w);
        ow[q * 2]     = *reinterpret_cast<uint32_t*>(&h0);
        ow[q * 2 + 1] = *reinterpret_cast<uint32_t*>(&h1);
        ssq = fmaf(v.x, v.x, ssq); ssq = fmaf(v.y, v.y, ssq);
        ssq = fmaf(v.z, v.z, ssq); ssq = fmaf(v.w, v.w, ssq);
    }
    uint4* dst = g_bimg + (size_t)n * 8;
    #pragma unroll
    for (int j = 0; j < 8; j++) dst[j] = outv[j];
    g_cbsq[n] = ssq;
    g_bias[n] = -0.5f * ssq;
}

// per-(chunk,k) max |c|, coalesced, no atomics
__global__ void cmax_kernel(const float* __restrict__ cb) {
    __shared__ float red[256];
    const int chunk = blockIdx.x;
    const int k = threadIdx.x & 63, part = threadIdx.x >> 6;
    const float* base = cb + (size_t)chunk * NCW * SUB;
    float m = 0.f;
    for (int r = part; r < NCW; r += 4)
        m = fmaxf(m, fabsf(base[(size_t)r * SUB + k]));
    red[threadIdx.x] = m;
    __syncthreads();
    if (threadIdx.x < 64) {
        m = fmaxf(fmaxf(red[threadIdx.x], red[threadIdx.x + 64]),
                  fmaxf(red[threadIdx.x + 128], red[threadIdx.x + 192]));
        g_cmax[chunk * 64 + threadIdx.x] = m;
    }
}

// ---------------------------------------------------------------------------
// main: HMMA fp16 filter + per-score top-2 gap proof + rare exact rescue
// grid (64, 16), 512 threads (16 warps). Warp w: M-group (w&7)*16 rows,
// N-half (w>>3). 2x the warps of R8 to hide LDSM/MMA latency chains.
// ---------------------------------------------------------------------------
__global__ __launch_bounds__(NTHR, 2)
void vq_kernel(const float* __restrict__ x, const float* __restrict__ cb,
               float* __restrict__ out) {
    extern __shared__ char sm[];
    const uint32_t smb = smem_u32(sm);
    const int tid = threadIdx.x, w = tid >> 5, lane = tid & 31;
    const int chunk = blockIdx.y;
    const int t0 = blockIdx.x * TM;
    const float* cbc = cb + (size_t)chunk * NCW * SUB;

    float* sBias = reinterpret_cast<float*>(sm + SM_BIAS);
    float* sXsq  = reinterpret_cast<float*>(sm + SM_XSQ);
    float* sEps  = reinterpret_cast<float*>(sm + SM_EPS);
    float* sMax  = reinterpret_cast<float*>(sm + SM_MAX);
    float* sT1   = reinterpret_cast<float*>(sm + SM_TOP);            // [2][128]
    float* sT2   = reinterpret_cast<float*>(sm + SM_TOP + 1024);     // [2][128]
    int*   sTI   = reinterpret_cast<int*>  (sm + SM_TOP + 2048);     // [2][128]

    // ---- build fp16 A tile + exact xsq + per-token error threshold ----
    // 4 threads per token row; thread (tid&3) handles 4 float4 = 16 floats
    {
        const int r = tid >> 2, h4 = tid & 3;
        const float4* xp = reinterpret_cast<const float4*>(
            x + (size_t)(t0 + r) * DIM + chunk * SUB + h4 * 16);
        const float4* cm4 = reinterpret_cast<const float4*>(
            g_cmax + chunk * 64 + h4 * 16);
        __half* arow = reinterpret_cast<__half*>(sm + SM_A + r * 144 + h4 * 32);
        float ssq = 0.f, sabs = 0.f;
        #pragma unroll
        for (int q = 0; q < 4; q++) {
            float4 v = xp[q];
            float4 cm = __ldg(cm4 + q);
            __half2* dh = reinterpret_cast<__half2*>(arow + q * 4);
            dh[0] = __floats2half2_rn(v.x, v.y);
            dh[1] = __floats2half2_rn(v.z, v.w);
            ssq = fmaf(v.x, v.x, ssq); ssq = fmaf(v.y, v.y, ssq);
            ssq = fmaf(v.z, v.z, ssq); ssq = fmaf(v.w, v.w, ssq);
            sabs = fmaf(fabsf(v.x), cm.x, sabs);
            sabs = fmaf(fabsf(v.y), cm.y, sabs);
            sabs = fmaf(fabsf(v.z), cm.z, sabs);
            sabs = fmaf(fabsf(v.w), cm.w, sabs);
        }
        ssq  += __shfl_xor_sync(0xffffffffu, ssq, 1);
        ssq  += __shfl_xor_sync(0xffffffffu, ssq, 2);
        sabs += __shfl_xor_sync(0xffffffffu, sabs, 1);
        sabs += __shfl_xor_sync(0xffffffffu, sabs, 2);
        if (h4 == 0) {
            sXsq[r] = ssq;
            // 2*eps: fp16 rounding (2^-10 * S) + fp32 accum slack + abs slack
            sEps[r] = 2.f * (0.001f * sabs + 2e-5f * (sabs + 64.f) + 1e-4f);
        }
    }
    // ---- copy B tile 0 + bias 0 (plain) ----
    {
        const uint4* src = g_bimg + (size_t)chunk * NCW * 8;
        #pragma unroll
        for (int r = 0; r < 2; r++) {
            int idx = r * NTHR + tid, n = idx >> 3, kq = idx & 7;
            *reinterpret_cast<uint4*>(sm + SM_B + n * 144 + kq * 16) = src[idx];
        }
        if (tid < 128) sBias[tid] = g_bias[chunk * NCW + tid];
    }
    __syncthreads();

    const int mg = w & 7;    // M group: token rows [mg*16, mg*16+16)
    const int ng = w >> 3;   // N half: subtiles s = 2*ng, 2*ng+1

    // ---- A fragments: 1 m16 block, registers for the whole kernel ----
    uint32_t aF[4][4];
    {
        const int aRow = ((lane >> 3) & 1) * 8 + (lane & 7);
        const int aK8  = lane >> 4;
        uint32_t abase = smb + SM_A + (mg * 16 + aRow) * 144 + aK8 * 16;
        #pragma unroll
        for (int kt = 0; kt < 4; kt++)
            ldsm4(aF[kt][0], aF[kt][1], aF[kt][2], aF[kt][3], abase + kt * 32);
    }

    const int bRow = ((lane >> 3) & 1) * 8 + (lane & 7);
    const uint32_t laneOffB = bRow * 144 + (lane >> 4) * 16;
    const int gid = lane >> 2, tidg = lane & 3;

    // per-lane top-2 trackers; slot 0 = row gid, slot 1 = row gid+8
    float t1v[2], t2v[2]; int t1i[2];
    #pragma unroll
    for (int i = 0; i < 2; i++) {
        t1v[i] = -3.4028235e38f; t2v[i] = -3.4028235e38f; t1i[i] = 0;
    }

    // ---- mainloop over 16 B tiles, double-buffered via cp.async ----
    for (int t = 0; t < NBT; t++) {
        const int buf = t & 1;
        if (t + 1 < NBT) {
            const uint4* src = g_bimg + ((size_t)chunk * NCW + (t + 1) * BT) * 8;
            const uint32_t dstb = smb + SM_B + (buf ^ 1) * 18432;
            #pragma unroll
            for (int r = 0; r < 2; r++) {
                int idx = r * NTHR + tid, n = idx >> 3, kq = idx & 7;
                cp16(dstb + n * 144 + kq * 16, src + idx);
            }
            if (tid < 128)
                cp4(smb + SM_BIAS + (buf ^ 1) * 512 + tid * 4,
                    g_bias + chunk * NCW + (t + 1) * BT + tid);
            CP_COMMIT();
        }

        const uint32_t bbase = smb + SM_B + buf * 18432 + laneOffB;
        const float* biasb = sBias + buf * 128;

        #pragma unroll
        for (int ss = 0; ss < 2; ss++) {
            const int s = ng * 2 + ss;
            float d[4][4];
            #pragma unroll
            for (int j = 0; j < 4; j++) {
                float2 bp = *reinterpret_cast<const float2*>(
                    biasb + s * 32 + j * 8 + tidg * 2);
                d[j][0] = bp.x; d[j][1] = bp.y;
                d[j][2] = bp.x; d[j][3] = bp.y;
            }
            #pragma unroll
            for (int kt = 0; kt < 4; kt++) {
                uint32_t b0, b1, b2, b3, b4, b5, b6, b7;
                uint32_t ad = bbase + s * (32 * 144) + kt * 32;
                ldsm4(b0, b1, b2, b3, ad);
                ldsm4(b4, b5, b6, b7, ad + 16 * 144);
                // ldmatrix.x4 order: {n0-7/klo, n8-15/klo, n0-7/khi, n8-15/khi}
                mma16816(d[0], aF[kt], b0, b2);   // n  0- 7
                mma16816(d[1], aF[kt], b1, b3);   // n  8-15
                mma16816(d[2], aF[kt], b4, b6);   // n 16-23
                mma16816(d[3], aF[kt], b5, b7);   // n 24-31
            }
            // per-score top-2 update + subtile max
            const int nb0 = t * 128 + s * 32 + tidg * 2;
            #pragma unroll
            for (int j = 0; j < 4; j++) {
                const int n0 = nb0 + j * 8;
                upd2(t1v[0], t1i[0], t2v[0], d[j][0], n0);
                upd2(t1v[0], t1i[0], t2v[0], d[j][1], n0 + 1);
                upd2(t1v[1], t1i[1], t2v[1], d[j][2], n0);
                upd2(t1v[1], t1i[1], t2v[1], d[j][3], n0 + 1);
            }
            float r0m = fmaxf(fmaxf(d[0][0], d[0][1]), fmaxf(d[1][0], d[1][1]));
            r0m = fmaxf(r0m, fmaxf(fmaxf(d[2][0], d[2][1]),
                                   fmaxf(d[3][0], d[3][1])));
            float r1m = fmaxf(fmaxf(d[0][2], d[0][3]), fmaxf(d[1][2], d[1][3]));
            r1m = fmaxf(r1m, fmaxf(fmaxf(d[2][2], d[2][3]),
                                   fmaxf(d[3][2], d[3][3])));
            r0m = fmaxf(r0m, __shfl_xor_sync(0xffffffffu, r0m, 1));
            r0m = fmaxf(r0m, __shfl_xor_sync(0xffffffffu, r0m, 2));
            r1m = fmaxf(r1m, __shfl_xor_sync(0xffffffffu, r1m, 1));
            r1m = fmaxf(r1m, __shfl_xor_sync(0xffffffffu, r1m, 2));
            if (tidg == 0) {
                const int sg  = t * 4 + s;
                const int row = mg * 16 + gid;
                sMax[sg * 128 + row]     = r0m;
                sMax[sg * 128 + row + 8] = r1m;
            }
        }
        CP_WAIT0();
        __syncthreads();
    }

    // ---- cross-lane/warp top-2 merge ----
    uint32_t* wl    = reinterpret_cast<uint32_t*>(sm + SM_WL);
    ull*      sBest = reinterpret_cast<ull*>(sm + SM_BEST);
    uint32_t* wcnt  = reinterpret_cast<uint32_t*>(sm + SM_WCNT);
    if (tid == 0) *wcnt = 0;

    #pragma unroll
    for (int sl = 0; sl < 2; sl++) {
        float av = t1v[sl], a2 = t2v[sl]; int ai = t1i[sl];
        #pragma unroll
        for (int off = 1; off <= 2; off <<= 1) {
            float bv = __shfl_xor_sync(0xffffffffu, av, off);
            int   bi = __shfl_xor_sync(0xffffffffu, ai, off);
            float b2 = __shfl_xor_sync(0xffffffffu, a2, off);
            if (bv > av) { a2 = fmaxf(av, b2); av = bv; ai = bi; }
            else         { a2 = fmaxf(a2, bv); }
        }
        if (tidg == 0) {
            const int row = mg * 16 + gid + sl * 8;
            sT1[ng * 128 + row] = av;
            sT2[ng * 128 + row] = a2;
            sTI[ng * 128 + row] = ai;
        }
    }
    __syncthreads();

    // ---- classify tokens: proven winner vs ambiguous (needs exact rescue) ----
    if (tid < 128) {
        float av = sT1[tid],       a2 = sT2[tid];       int ai = sTI[tid];
        float bv = sT1[128 + tid], b2 = sT2[128 + tid]; int bi = sTI[128 + tid];
        float gt1, gt2; int gti;
        if (bv > av) { gt1 = bv; gti = bi; gt2 = fmaxf(av, b2); }
        else         { gt1 = av; gti = ai; gt2 = fmaxf(a2, bv); }
        const float thr2 = sEps[tid];
        if (gt1 - gt2 > thr2) {
            sBest[tid] = (ull)(uint32_t)gti;      // proven exact winner
        } else {
            sBest[tid] = ~0ull;
            const float cth = gt1 - thr2;
            for (int s2 = 0; s2 < 64; s2++)
                if (sMax[s2 * 128 + tid] >= cth) {
                    uint32_t p = atomicAdd(wcnt, 1u);
                    wl[p] = ((uint32_t)tid << 8) | (uint32_t)s2;
                }
        }
    }
    __syncthreads();

    // ---- exact fp32 rescue (rare; R1-identical arithmetic) ----
    const int cnt = *wcnt;
    const float* cqc = g_cbsq + chunk * NCW;
    for (int it = w; it < cnt; it += 16) {
        const uint32_t item = wl[it];
        const int tk = item >> 8, st = item & 255;
        const int n = st * 32 + lane;
        const float4* cp = reinterpret_cast<const float4*>(cbc + (size_t)n * SUB);
        const float4* xv = reinterpret_cast<const float4*>(
            x + (size_t)(t0 + tk) * DIM + chunk * SUB);
        float acc = 0.f;
        #pragma unroll
        for (int q = 0; q < 16; q++) {
            float4 c4 = __ldg(cp + q);
            float4 x4 = xv[q];
            acc = fmaf(c4.x, x4.x, acc);
            acc = fmaf(c4.y, x4.y, acc);
            acc = fmaf(c4.z, x4.z, acc);
            acc = fmaf(c4.w, x4.w, acc);
        }
        const float d2 = fmaf(-2.f, acc, sXsq[tk]) + __ldg(&cqc[n]);
        const ull key = ((ull)ord_f32(d2) << 32) | (uint32_t)n;
        atomicMin(&sBest[tk], key);
    }
    __syncthreads();

    // ---- gather winning codewords (4 threads per token row) ----
    {
        const int r = tid >> 2, h4 = tid & 3;
        const uint32_t n = (uint32_t)(sBest[r] & 0xFFFFFFFFull);
        const float4* src = reinterpret_cast<const float4*>(
            cbc + (size_t)n * SUB + h4 * 16);
        float4* dst = reinterpret_cast<float4*>(
            out + (size_t)(t0 + r) * DIM + chunk * SUB + h4 * 16);
        #pragma unroll
        for (int q = 0; q < 4; q++) dst[q] = src[q];
    }
}

extern "C" void kernel_launch(void* const* d_in, const int* in_sizes, int n_in,
                              void* d_out, int out_size) {
    (void)n_in; (void)out_size;
    const float* x  = (const float*)d_in[0];   // (4,2048,1024) fp32
    const float* cb = (const float*)d_in[1];   // (16,2048,64) fp32
    float* out = (float*)d_out;
    const int tokens = in_sizes[0] / DIM;      // 8192

    cudaFuncSetAttribute(vq_kernel,
                         cudaFuncAttributeMaxDynamicSharedMemorySize, SM_TOTAL);

    prep_kernel<<<C_CHUNKS * NCW / 256, 256>>>(cb);
    cmax_kernel<<<C_CHUNKS, 256>>>(cb);
    dim3 grid(tokens / TM, C_CHUNKS);
    vq_kernel<<<grid, NTHR, SM_TOTAL>>>(x, cb, out);
}

// round 10
// speedup vs baseline: 1.0744x; 1.0744x over previous
#include <cuda_runtime.h>
#include <cuda_fp16.h>
#include <stdint.h>

#define C_CHUNKS 16
#define NCW      2048
#define SUB      64
#define DIM      1024
#define TM       128
#define BT       128            // codewords per B tile
#define NBT      (NCW / BT)     // 16

// smem layout (bytes)
#define SM_A     0              // 128 x 144B = 18432 (A staging for ldmatrix)
#define SM_BIAS  18432          // 2048 f32 = 8192 (all tiles' biases)
#define SM_XSQ   26624          // 128 f32
#define SM_EPS   27136          // 128 f32
#define SM_MAX   27648          // 64 x 128 f32 = 32768
#define SM_TOP   60416          // 3 x 256 = 3072
#define SM_WL    63488          // 8192 x u32 = 32768 (worst case)
#define SM_BEST  96256          // 128 x u64 = 1024
#define SM_WCNT  97280
#define SM_TOTAL 97312

typedef unsigned long long ull;

__device__ float g_cbsq[C_CHUNKS * NCW];
__device__ float g_bias[C_CHUNKS * NCW];
__device__ float g_cmax[C_CHUNKS * SUB];       // per (chunk,k) max |c|
// B in MMA *fragment order*: [(chunk*16+t)*16 + s*4 + kt] blocks of 64 uint4:
//   [lane]      = {b0,b1,b2,b3}  (n 0-15 of subtile)
//   [32 + lane] = {b4,b5,b6,b7}  (n 16-31 of subtile)
__device__ uint4 g_bfrag[C_CHUNKS * NBT * 16 * 64];

// ---------------------------------------------------------------------------
__device__ __forceinline__ uint32_t smem_u32(const void* p) {
    uint32_t a;
    asm("{ .reg .u64 t; cvta.to.shared.u64 t, %1; cvt.u32.u64 %0, t; }"
        : "=r"(a) : "l"(p));
    return a;
}
__device__ __forceinline__ void ldsm4(uint32_t& r0, uint32_t& r1, uint32_t& r2,
                                      uint32_t& r3, uint32_t a) {
    asm volatile("ldmatrix.sync.aligned.m8n8.x4.shared.b16 {%0,%1,%2,%3}, [%4];"
                 : "=r"(r0), "=r"(r1), "=r"(r2), "=r"(r3) : "r"(a));
}
__device__ __forceinline__ void mma16816(float* d, const uint32_t* a,
                                         uint32_t b0, uint32_t b1) {
    asm volatile(
        "mma.sync.aligned.m16n8k16.row.col.f32.f16.f16.f32 "
        "{%0,%1,%2,%3}, {%4,%5,%6,%7}, {%8,%9}, {%0,%1,%2,%3};"
        : "+f"(d[0]), "+f"(d[1]), "+f"(d[2]), "+f"(d[3])
        : "r"(a[0]), "r"(a[1]), "r"(a[2]), "r"(a[3]), "r"(b0), "r"(b1));
}
__device__ __forceinline__ uint32_t ord_f32(float f) {
    uint32_t u = __float_as_uint(f);
    return (u & 0x80000000u) ? ~u : (u | 0x80000000u);
}
// top-2 update, select form
__device__ __forceinline__ void upd2(float& t1, int& ti, float& t2,
                                     float v, int n) {
    const bool g = v > t1;
    t2 = g ? t1 : fmaxf(t2, v);
    ti = g ? n : ti;
    t1 = g ? v : t1;
}

// ---------------------------------------------------------------------------
// prep: per (chunk, tile) block: fp16-convert codewords into an LDSM-layout
// smem stage, then ldmatrix them ONCE and dump the warp registers to g_bfrag
// in lane-major order (bit-identical fragments to the R8 mainloop's).
// Also emits cbsq + bias. grid 256 (chunk*16+t), 256 threads.
// ---------------------------------------------------------------------------
__global__ void prep_kernel(const float* __restrict__ cb) {
    extern __shared__ char sm[];
    const uint32_t smb = smem_u32(sm);
    const int tid = threadIdx.x, w = tid >> 5, lane = tid & 31;
    const int chunk = blockIdx.x >> 4, t = blockIdx.x & 15;

    // stage: row n (128 cw) x 64 k as fp16, 144B row stride
    {
        const int r = tid >> 1, h = tid & 1;
        const int n = chunk * NCW + t * BT + r;
        const float4* cp = reinterpret_cast<const float4*>(
            cb + (size_t)n * SUB + h * 32);
        __half* row = reinterpret_cast<__half*>(sm + r * 144 + h * 64);
        float ssq = 0.f;
        #pragma unroll
        for (int q = 0; q < 8; q++) {
            float4 v = cp[q];
            __half2* dh = reinterpret_cast<__half2*>(row + q * 4);
            dh[0] = __floats2half2_rn(v.x, v.y);
            dh[1] = __floats2half2_rn(v.z, v.w);
            ssq = fmaf(v.x, v.x, ssq); ssq = fmaf(v.y, v.y, ssq);
            ssq = fmaf(v.z, v.z, ssq); ssq = fmaf(v.w, v.w, ssq);
        }
        ssq += __shfl_xor_sync(0xffffffffu, ssq, 1);
        if (h == 0) {
            g_cbsq[n] = ssq;
            g_bias[n] = -0.5f * ssq;
        }
    }
    __syncthreads();

    // warp w: subtile s = w>>1, kt pair = (w&1)*2
    const int s = w >> 1;
    const int bRow = ((lane >> 3) & 1) * 8 + (lane & 7);
    const uint32_t laneOff = bRow * 144 + (lane >> 4) * 16;
    #pragma unroll
    for (int ktl = 0; ktl < 2; ktl++) {
        const int kt = (w & 1) * 2 + ktl;
        uint32_t b0, b1, b2, b3, b4, b5, b6, b7;
        uint32_t ad = smb + s * (32 * 144) + kt * 32 + laneOff;
        ldsm4(b0, b1, b2, b3, ad);
        ldsm4(b4, b5, b6, b7, ad + 16 * 144);
        uint4* dst = g_bfrag + ((size_t)(blockIdx.x * 16 + s * 4 + kt)) * 64;
        dst[lane]      = make_uint4(b0, b1, b2, b3);
        dst[32 + lane] = make_uint4(b4, b5, b6, b7);
    }
}

// per-(chunk,k) max |c|, coalesced, no atomics
__global__ void cmax_kernel(const float* __restrict__ cb) {
    __shared__ float red[256];
    const int chunk = blockIdx.x;
    const int k = threadIdx.x & 63, part = threadIdx.x >> 6;
    const float* base = cb + (size_t)chunk * NCW * SUB;
    float m = 0.f;
    for (int r = part; r < NCW; r += 4)
        m = fmaxf(m, fabsf(base[(size_t)r * SUB + k]));
    red[threadIdx.x] = m;
    __syncthreads();
    if (threadIdx.x < 64) {
        m = fmaxf(fmaxf(red[threadIdx.x], red[threadIdx.x + 64]),
                  fmaxf(red[threadIdx.x + 128], red[threadIdx.x + 192]));
        g_cmax[chunk * 64 + threadIdx.x] = m;
    }
}

// ---------------------------------------------------------------------------
// main: HMMA filter with B fragments LDG'd straight to registers (no smem B,
// no cp.async, NO barriers in the mainloop) + top-2 gap proof + exact rescue.
// grid (64, 16), 256 threads. Warp w: M-group (w&3)*32, N-half (w>>2).
// ---------------------------------------------------------------------------
__global__ __launch_bounds__(256, 2)
void vq_kernel(const float* __restrict__ x, const float* __restrict__ cb,
               float* __restrict__ out) {
    extern __shared__ char sm[];
    const uint32_t smb = smem_u32(sm);
    const int tid = threadIdx.x, w = tid >> 5, lane = tid & 31;
    const int chunk = blockIdx.y;
    const int t0 = blockIdx.x * TM;
    const float* cbc = cb + (size_t)chunk * NCW * SUB;

    float* sBias = reinterpret_cast<float*>(sm + SM_BIAS);   // 2048 floats
    float* sXsq  = reinterpret_cast<float*>(sm + SM_XSQ);
    float* sEps  = reinterpret_cast<float*>(sm + SM_EPS);
    float* sMax  = reinterpret_cast<float*>(sm + SM_MAX);
    float* sT1   = reinterpret_cast<float*>(sm + SM_TOP);            // [2][128]
    float* sT2   = reinterpret_cast<float*>(sm + SM_TOP + 1024);     // [2][128]
    int*   sTI   = reinterpret_cast<int*>  (sm + SM_TOP + 2048);     // [2][128]

    // ---- build fp16 A tile + exact xsq + per-token error threshold ----
    {
        const int r = tid >> 1, h = tid & 1;
        const float4* xp = reinterpret_cast<const float4*>(
            x + (size_t)(t0 + r) * DIM + chunk * SUB + h * 32);
        const float4* cm4 = reinterpret_cast<const float4*>(
            g_cmax + chunk * 64 + h * 32);
        __half* arow = reinterpret_cast<__half*>(sm + SM_A + r * 144 + h * 64);
        float ssq = 0.f, sabs = 0.f;
        #pragma unroll
        for (int q = 0; q < 8; q++) {
            float4 v = xp[q];
            float4 cm = __ldg(cm4 + q);
            __half2* dh = reinterpret_cast<__half2*>(arow + q * 4);
            dh[0] = __floats2half2_rn(v.x, v.y);
            dh[1] = __floats2half2_rn(v.z, v.w);
            ssq = fmaf(v.x, v.x, ssq); ssq = fmaf(v.y, v.y, ssq);
            ssq = fmaf(v.z, v.z, ssq); ssq = fmaf(v.w, v.w, ssq);
            sabs = fmaf(fabsf(v.x), cm.x, sabs);
            sabs = fmaf(fabsf(v.y), cm.y, sabs);
            sabs = fmaf(fabsf(v.z), cm.z, sabs);
            sabs = fmaf(fabsf(v.w), cm.w, sabs);
        }
        ssq  += __shfl_xor_sync(0xffffffffu, ssq, 1);
        sabs += __shfl_xor_sync(0xffffffffu, sabs, 1);
        if (h == 0) {
            sXsq[r] = ssq;
            // 2*eps: fp16 rounding (2^-10 * S) + fp32 accum slack + abs slack
            sEps[r] = 2.f * (0.001f * sabs + 2e-5f * (sabs + 64.f) + 1e-4f);
        }
    }
    // ---- preload ALL tile biases once (2048 f32) ----
    #pragma unroll
    for (int i = 0; i < 8; i++)
        sBias[i * 256 + tid] = g_bias[chunk * NCW + i * 256 + tid];
    __syncthreads();

    const int mg = w & 3;    // M group: token rows [mg*32, mg*32+32)
    const int ng = w >> 2;   // N half: subtiles s = 2*ng, 2*ng+1

    // ---- A fragments: 2 m16 blocks, registers for the whole kernel ----
    uint32_t aF[2][4][4];
    {
        const int aRow = ((lane >> 3) & 1) * 8 + (lane & 7);
        const int aK8  = lane >> 4;
        #pragma unroll
        for (int mb = 0; mb < 2; mb++) {
            uint32_t abase = smb + SM_A + (mg * 32 + mb * 16 + aRow) * 144
                           + aK8 * 16;
            #pragma unroll
            for (int kt = 0; kt < 4; kt++)
                ldsm4(aF[mb][kt][0], aF[mb][kt][1], aF[mb][kt][2],
                      aF[mb][kt][3], abase + kt * 32);
        }
    }

    const int gid = lane >> 2, tidg = lane & 3;

    // per-lane top-2 trackers; slot = mb*2 + half (half1 = row+8)
    float t1v[4], t2v[4]; int t1i[4];
    #pragma unroll
    for (int i = 0; i < 4; i++) {
        t1v[i] = -3.4028235e38f; t2v[i] = -3.4028235e38f; t1i[i] = 0;
    }

    // ---- mainloop: 16 tiles x 2 subtiles, ZERO barriers ----
    const uint4* fragc = g_bfrag + (size_t)chunk * NBT * 16 * 64;
    for (int t = 0; t < NBT; t++) {
        #pragma unroll
        for (int ss = 0; ss < 2; ss++) {
            const int s = ng * 2 + ss;
            const uint4* fb = fragc + (size_t)(t * 16 + s * 4) * 64 + lane;

            // load all 8 fragment vectors for this subtile (MLP=8)
            uint4 f[8];
            #pragma unroll
            for (int kt = 0; kt < 4; kt++) {
                f[kt * 2]     = __ldg(fb + kt * 64);
                f[kt * 2 + 1] = __ldg(fb + kt * 64 + 32);
            }

            float d[2][4][4];
            #pragma unroll
            for (int j = 0; j < 4; j++) {
                float2 bp = *reinterpret_cast<const float2*>(
                    sBias + t * 128 + s * 32 + j * 8 + tidg * 2);
                #pragma unroll
                for (int mb = 0; mb < 2; mb++) {
                    d[mb][j][0] = bp.x; d[mb][j][1] = bp.y;
                    d[mb][j][2] = bp.x; d[mb][j][3] = bp.y;
                }
            }
            #pragma unroll
            for (int kt = 0; kt < 4; kt++) {
                const uint4 u1 = f[kt * 2], u2 = f[kt * 2 + 1];
                #pragma unroll
                for (int mb = 0; mb < 2; mb++) {
                    mma16816(d[mb][0], aF[mb][kt], u1.x, u1.z);   // n  0- 7
                    mma16816(d[mb][1], aF[mb][kt], u1.y, u1.w);   // n  8-15
                    mma16816(d[mb][2], aF[mb][kt], u2.x, u2.z);   // n 16-23
                    mma16816(d[mb][3], aF[mb][kt], u2.y, u2.w);   // n 24-31
                }
            }
            // per-score top-2 update + subtile max
            const int nb0 = t * 128 + s * 32 + tidg * 2;
            #pragma unroll
            for (int mb = 0; mb < 2; mb++) {
                #pragma unroll
                for (int j = 0; j < 4; j++) {
                    const int n0 = nb0 + j * 8;
                    upd2(t1v[mb*2],   t1i[mb*2],   t2v[mb*2],   d[mb][j][0], n0);
                    upd2(t1v[mb*2],   t1i[mb*2],   t2v[mb*2],   d[mb][j][1], n0+1);
                    upd2(t1v[mb*2+1], t1i[mb*2+1], t2v[mb*2+1], d[mb][j][2], n0);
                    upd2(t1v[mb*2+1], t1i[mb*2+1], t2v[mb*2+1], d[mb][j][3], n0+1);
                }
                float r0m = fmaxf(fmaxf(d[mb][0][0], d[mb][0][1]),
                                  fmaxf(d[mb][1][0], d[mb][1][1]));
                r0m = fmaxf(r0m, fmaxf(fmaxf(d[mb][2][0], d[mb][2][1]),
                                       fmaxf(d[mb][3][0], d[mb][3][1])));
                float r1m = fmaxf(fmaxf(d[mb][0][2], d[mb][0][3]),
                                  fmaxf(d[mb][1][2], d[mb][1][3]));
                r1m = fmaxf(r1m, fmaxf(fmaxf(d[mb][2][2], d[mb][2][3]),
                                       fmaxf(d[mb][3][2], d[mb][3][3])));
                r0m = fmaxf(r0m, __shfl_xor_sync(0xffffffffu, r0m, 1));
                r0m = fmaxf(r0m, __shfl_xor_sync(0xffffffffu, r0m, 2));
                r1m = fmaxf(r1m, __shfl_xor_sync(0xffffffffu, r1m, 1));
                r1m = fmaxf(r1m, __shfl_xor_sync(0xffffffffu, r1m, 2));
                if (tidg == 0) {
                    const int sg  = t * 4 + s;
                    const int row = mg * 32 + mb * 16 + gid;
                    sMax[sg * 128 + row]     = r0m;
                    sMax[sg * 128 + row + 8] = r1m;
                }
            }
        }
    }

    // ---- cross-lane/warp top-2 merge ----
    uint32_t* wl    = reinterpret_cast<uint32_t*>(sm + SM_WL);
    ull*      sBest = reinterpret_cast<ull*>(sm + SM_BEST);
    uint32_t* wcnt  = reinterpret_cast<uint32_t*>(sm + SM_WCNT);
    if (tid == 0) *wcnt = 0;

    #pragma unroll
    for (int sl = 0; sl < 4; sl++) {
        float av = t1v[sl], a2 = t2v[sl]; int ai = t1i[sl];
        #pragma unroll
        for (int off = 1; off <= 2; off <<= 1) {
            float bv = __shfl_xor_sync(0xffffffffu, av, off);
            int   bi = __shfl_xor_sync(0xffffffffu, ai, off);
            float b2 = __shfl_xor_sync(0xffffffffu, a2, off);
            if (bv > av) { a2 = fmaxf(av, b2); av = bv; ai = bi; }
            else         { a2 = fmaxf(a2, bv); }
        }
        if (tidg == 0) {
            const int row = mg * 32 + (sl >> 1) * 16 + gid + (sl & 1) * 8;
            sT1[ng * 128 + row] = av;
            sT2[ng * 128 + row] = a2;
            sTI[ng * 128 + row] = ai;
        }
    }
    __syncthreads();

    // ---- classify tokens: proven winner vs ambiguous (needs exact rescue) ----
    if (tid < 128) {
        float av = sT1[tid],       a2 = sT2[tid];       int ai = sTI[tid];
        float bv = sT1[128 + tid], b2 = sT2[128 + tid]; int bi = sTI[128 + tid];
        float gt1, gt2; int gti;
        if (bv > av) { gt1 = bv; gti = bi; gt2 = fmaxf(av, b2); }
        else         { gt1 = av; gti = ai; gt2 = fmaxf(a2, bv); }
        const float thr2 = sEps[tid];
        if (gt1 - gt2 > thr2) {
            sBest[tid] = (ull)(uint32_t)gti;      // proven exact winner
        } else {
            sBest[tid] = ~0ull;
            const float cth = gt1 - thr2;
            for (int s2 = 0; s2 < 64; s2++)
                if (sMax[s2 * 128 + tid] >= cth) {
                    uint32_t p = atomicAdd(wcnt, 1u);
                    wl[p] = ((uint32_t)tid << 8) | (uint32_t)s2;
                }
        }
    }
    __syncthreads();

    // ---- exact fp32 rescue (rare; R1-identical arithmetic) ----
    const int cnt = *wcnt;
    const float* cqc = g_cbsq + chunk * NCW;
    for (int it = w; it < cnt; it += 8) {
        const uint32_t item = wl[it];
        const int tk = item >> 8, st = item & 255;
        const int n = st * 32 + lane;
        const float4* cp = reinterpret_cast<const float4*>(cbc + (size_t)n * SUB);
        const float4* xv = reinterpret_cast<const float4*>(
            x + (size_t)(t0 + tk) * DIM + chunk * SUB);
        float acc = 0.f;
        #pragma unroll
        for (int q = 0; q < 16; q++) {
            float4 c4 = __ldg(cp + q);
            float4 x4 = xv[q];
            acc = fmaf(c4.x, x4.x, acc);
            acc = fmaf(c4.y, x4.y, acc);
            acc = fmaf(c4.z, x4.z, acc);
            acc = fmaf(c4.w, x4.w, acc);
        }
        const float d2 = fmaf(-2.f, acc, sXsq[tk]) + __ldg(&cqc[n]);
        const ull key = ((ull)ord_f32(d2) << 32) | (uint32_t)n;
        atomicMin(&sBest[tk], key);
    }
    __syncthreads();

    // ---- gather winning codewords ----
    {
        const int r = tid >> 1, h = tid & 1;
        const uint32_t n = (uint32_t)(sBest[r] & 0xFFFFFFFFull);
        const float4* src = reinterpret_cast<const float4*>(
            cbc + (size_t)n * SUB + h * 32);
        float4* dst = reinterpret_cast<float4*>(
            out + (size_t)(t0 + r) * DIM + chunk * SUB + h * 32);
        #pragma unroll
        for (int q = 0; q < 8; q++) dst[q] = src[q];
    }
}

extern "C" void kernel_launch(void* const* d_in, const int* in_sizes, int n_in,
                              void* d_out, int out_size) {
    (void)n_in; (void)out_size;
    const float* x  = (const float*)d_in[0];   // (4,2048,1024) fp32
    const float* cb = (const float*)d_in[1];   // (16,2048,64) fp32
    float* out = (float*)d_out;
    const int tokens = in_sizes[0] / DIM;      // 8192

    cudaFuncSetAttribute(vq_kernel,
                         cudaFuncAttributeMaxDynamicSharedMemorySize, SM_TOTAL);

    prep_kernel<<<C_CHUNKS * NBT, 256, 18432>>>(cb);
    cmax_kernel<<<C_CHUNKS, 256>>>(cb);
    dim3 grid(tokens / TM, C_CHUNKS);
    vq_kernel<<<grid, 256, SM_TOTAL>>>(x, cb, out);
}

// round 11
// speedup vs baseline: 1.0897x; 1.0142x over previous
#include <cuda_runtime.h>
#include <cuda_fp16.h>
#include <stdint.h>

#define C_CHUNKS 16
#define NCW      2048
#define SUB      64
#define DIM      1024
#define TM       128
#define BT       128            // codewords per B tile
#define NBT      (NCW / BT)     // 16

// smem layout (bytes)
#define SM_A     0              // 128 x 144B = 18432 (A staging for ldmatrix)
#define SM_BIAS  18432          // 2048 f32 = 8192 (all tiles' biases)
#define SM_XSQ   26624          // 128 f32
#define SM_EPS   27136          // 128 f32
#define SM_MAX   27648          // 64 x 128 f32 = 32768
#define SM_TOP   60416          // 3 x 256 = 3072
#define SM_WL    63488          // 8192 x u32 = 32768 (worst case)
#define SM_BEST  96256          // 128 x u64 = 1024
#define SM_WCNT  97280
#define SM_TOTAL 97312

typedef unsigned long long ull;

__device__ float    g_cbsq[C_CHUNKS * NCW];
__device__ float    g_bias[C_CHUNKS * NCW];
__device__ unsigned g_cmaxu[C_CHUNKS * SUB];   // per (chunk,k) max |c| (f32 bits)
// B in MMA *fragment order*: [(chunk*16+t)*16 + s*4 + kt] blocks of 64 uint4:
//   [lane]      = {b0,b1,b2,b3}  (n 0-15 of subtile)
//   [32 + lane] = {b4,b5,b6,b7}  (n 16-31 of subtile)
__device__ uint4 g_bfrag[C_CHUNKS * NBT * 16 * 64];

// ---------------------------------------------------------------------------
__device__ __forceinline__ uint32_t smem_u32(const void* p) {
    uint32_t a;
    asm("{ .reg .u64 t; cvta.to.shared.u64 t, %1; cvt.u32.u64 %0, t; }"
        : "=r"(a) : "l"(p));
    return a;
}
__device__ __forceinline__ void ldsm4(uint32_t& r0, uint32_t& r1, uint32_t& r2,
                                      uint32_t& r3, uint32_t a) {
    asm volatile("ldmatrix.sync.aligned.m8n8.x4.shared.b16 {%0,%1,%2,%3}, [%4];"
                 : "=r"(r0), "=r"(r1), "=r"(r2), "=r"(r3) : "r"(a));
}
__device__ __forceinline__ void mma16816(float* d, const uint32_t* a,
                                         uint32_t b0, uint32_t b1) {
    asm volatile(
        "mma.sync.aligned.m16n8k16.row.col.f32.f16.f16.f32 "
        "{%0,%1,%2,%3}, {%4,%5,%6,%7}, {%8,%9}, {%0,%1,%2,%3};"
        : "+f"(d[0]), "+f"(d[1]), "+f"(d[2]), "+f"(d[3])
        : "r"(a[0]), "r"(a[1]), "r"(a[2]), "r"(a[3]), "r"(b0), "r"(b1));
}
__device__ __forceinline__ void prefetchL1(const void* p) {
    asm volatile("prefetch.global.L1 [%0];" :: "l"(p));
}
__device__ __forceinline__ uint32_t ord_f32(float f) {
    uint32_t u = __float_as_uint(f);
    return (u & 0x80000000u) ? ~u : (u | 0x80000000u);
}
// top-2 update, select form
__device__ __forceinline__ void upd2(float& t1, int& ti, float& t2,
                                     float v, int n) {
    const bool g = v > t1;
    t2 = g ? t1 : fmaxf(t2, v);
    ti = g ? n : ti;
    t1 = g ? v : t1;
}

// ---------------------------------------------------------------------------
// prep: per (chunk, tile) block: fp16-convert codewords into an LDSM-layout
// smem stage, ldmatrix ONCE, dump warp registers to g_bfrag (bit-identical
// fragments to the mainloop's). Also emits cbsq + bias + per-k |c| max
// (block-reduced + atomicMax; idempotent => graph-replay deterministic).
// grid 256 (chunk*16+t), 256 threads.
// ---------------------------------------------------------------------------
__global__ void prep_kernel(const float* __restrict__ cb) {
    extern __shared__ char sm[];
    __shared__ float red[256];
    const uint32_t smb = smem_u32(sm);
    const int tid = threadIdx.x, w = tid >> 5, lane = tid & 31;
    const int chunk = blockIdx.x >> 4, t = blockIdx.x & 15;

    // stage: row n (128 cw) x 64 k as fp16, 144B row stride
    {
        const int r = tid >> 1, h = tid & 1;
        const int n = chunk * NCW + t * BT + r;
        const float4* cp = reinterpret_cast<const float4*>(
            cb + (size_t)n * SUB + h * 32);
        __half* row = reinterpret_cast<__half*>(sm + r * 144 + h * 64);
        float ssq = 0.f;
        #pragma unroll
        for (int q = 0; q < 8; q++) {
            float4 v = cp[q];
            __half2* dh = reinterpret_cast<__half2*>(row + q * 4);
            dh[0] = __floats2half2_rn(v.x, v.y);
            dh[1] = __floats2half2_rn(v.z, v.w);
            ssq = fmaf(v.x, v.x, ssq); ssq = fmaf(v.y, v.y, ssq);
            ssq = fmaf(v.z, v.z, ssq); ssq = fmaf(v.w, v.w, ssq);
        }
        ssq += __shfl_xor_sync(0xffffffffu, ssq, 1);
        if (h == 0) {
            g_cbsq[n] = ssq;
            g_bias[n] = -0.5f * ssq;
        }
    }
    __syncthreads();

    // warp w: subtile s = w>>1, kt pair = (w&1)*2
    {
        const int s = w >> 1;
        const int bRow = ((lane >> 3) & 1) * 8 + (lane & 7);
        const uint32_t laneOff = bRow * 144 + (lane >> 4) * 16;
        #pragma unroll
        for (int ktl = 0; ktl < 2; ktl++) {
            const int kt = (w & 1) * 2 + ktl;
            uint32_t b0, b1, b2, b3, b4, b5, b6, b7;
            uint32_t ad = smb + s * (32 * 144) + kt * 32 + laneOff;
            ldsm4(b0, b1, b2, b3, ad);
            ldsm4(b4, b5, b6, b7, ad + 16 * 144);
            uint4* dst = g_bfrag + ((size_t)(blockIdx.x * 16 + s * 4 + kt)) * 64;
            dst[lane]      = make_uint4(b0, b1, b2, b3);
            dst[32 + lane] = make_uint4(b4, b5, b6, b7);
        }
    }

    // per-k |c| max over this block's 128 rows, then atomicMax to global
    {
        const int k = tid & 63, part = tid >> 6;
        const float* base = cb + ((size_t)chunk * NCW + t * BT) * SUB;
        float m = 0.f;
        for (int r = part; r < BT; r += 4)
            m = fmaxf(m, fabsf(base[(size_t)r * SUB + k]));
        red[tid] = m;
        __syncthreads();
        if (tid < 64) {
            m = fmaxf(fmaxf(red[tid], red[tid + 64]),
                      fmaxf(red[tid + 128], red[tid + 192]));
            atomicMax(&g_cmaxu[chunk * 64 + tid], __float_as_uint(m));
        }
    }
}

// ---------------------------------------------------------------------------
// main: HMMA filter with B fragments LDG'd straight to registers (no smem B,
// NO barriers in the mainloop), next-subtile prefetch.global.L1 to hide L2
// latency, top-2 gap proof + exact rescue.
// grid (64, 16), 256 threads. Warp w: M-group (w&3)*32, N-half (w>>2).
// ---------------------------------------------------------------------------
__global__ __launch_bounds__(256, 2)
void vq_kernel(const float* __restrict__ x, const float* __restrict__ cb,
               float* __restrict__ out) {
    extern __shared__ char sm[];
    const uint32_t smb = smem_u32(sm);
    const int tid = threadIdx.x, w = tid >> 5, lane = tid & 31;
    const int chunk = blockIdx.y;
    const int t0 = blockIdx.x * TM;
    const float* cbc = cb + (size_t)chunk * NCW * SUB;

    float* sBias = reinterpret_cast<float*>(sm + SM_BIAS);   // 2048 floats
    float* sXsq  = reinterpret_cast<float*>(sm + SM_XSQ);
    float* sEps  = reinterpret_cast<float*>(sm + SM_EPS);
    float* sMax  = reinterpret_cast<float*>(sm + SM_MAX);
    float* sT1   = reinterpret_cast<float*>(sm + SM_TOP);            // [2][128]
    float* sT2   = reinterpret_cast<float*>(sm + SM_TOP + 1024);     // [2][128]
    int*   sTI   = reinterpret_cast<int*>  (sm + SM_TOP + 2048);     // [2][128]

    // ---- build fp16 A tile + exact xsq + per-token error threshold ----
    {
        const int r = tid >> 1, h = tid & 1;
        const float4* xp = reinterpret_cast<const float4*>(
            x + (size_t)(t0 + r) * DIM + chunk * SUB + h * 32);
        const uint4* cm4 = reinterpret_cast<const uint4*>(
            g_cmaxu + chunk * 64 + h * 32);
        __half* arow = reinterpret_cast<__half*>(sm + SM_A + r * 144 + h * 64);
        float ssq = 0.f, sabs = 0.f;
        #pragma unroll
        for (int q = 0; q < 8; q++) {
            float4 v = xp[q];
            uint4 cmu = __ldg(cm4 + q);
            __half2* dh = reinterpret_cast<__half2*>(arow + q * 4);
            dh[0] = __floats2half2_rn(v.x, v.y);
            dh[1] = __floats2half2_rn(v.z, v.w);
            ssq = fmaf(v.x, v.x, ssq); ssq = fmaf(v.y, v.y, ssq);
            ssq = fmaf(v.z, v.z, ssq); ssq = fmaf(v.w, v.w, ssq);
            sabs = fmaf(fabsf(v.x), __uint_as_float(cmu.x), sabs);
            sabs = fmaf(fabsf(v.y), __uint_as_float(cmu.y), sabs);
            sabs = fmaf(fabsf(v.z), __uint_as_float(cmu.z), sabs);
            sabs = fmaf(fabsf(v.w), __uint_as_float(cmu.w), sabs);
        }
        ssq  += __shfl_xor_sync(0xffffffffu, ssq, 1);
        sabs += __shfl_xor_sync(0xffffffffu, sabs, 1);
        if (h == 0) {
            sXsq[r] = ssq;
            // 2*eps: fp16 rounding (2^-10 * S) + fp32 accum slack + abs slack
            sEps[r] = 2.f * (0.001f * sabs + 2e-5f * (sabs + 64.f) + 1e-4f);
        }
    }
    // ---- preload ALL tile biases once (2048 f32) ----
    #pragma unroll
    for (int i = 0; i < 8; i++)
        sBias[i * 256 + tid] = g_bias[chunk * NCW + i * 256 + tid];
    __syncthreads();

    const int mg = w & 3;    // M group: token rows [mg*32, mg*32+32)
    const int ng = w >> 2;   // N half: subtiles s = 2*ng, 2*ng+1

    // ---- A fragments: 2 m16 blocks, registers for the whole kernel ----
    uint32_t aF[2][4][4];
    {
        const int aRow = ((lane >> 3) & 1) * 8 + (lane & 7);
        const int aK8  = lane >> 4;
        #pragma unroll
        for (int mb = 0; mb < 2; mb++) {
            uint32_t abase = smb + SM_A + (mg * 32 + mb * 16 + aRow) * 144
                           + aK8 * 16;
            #pragma unroll
            for (int kt = 0; kt < 4; kt++)
                ldsm4(aF[mb][kt][0], aF[mb][kt][1], aF[mb][kt][2],
                      aF[mb][kt][3], abase + kt * 32);
        }
    }

    const int gid = lane >> 2, tidg = lane & 3;

    // per-lane top-2 trackers; slot = mb*2 + half (half1 = row+8)
    float t1v[4], t2v[4]; int t1i[4];
    #pragma unroll
    for (int i = 0; i < 4; i++) {
        t1v[i] = -3.4028235e38f; t2v[i] = -3.4028235e38f; t1i[i] = 0;
    }

    // ---- mainloop: 16 tiles x 2 subtiles, ZERO barriers ----
    const uint4* fragc = g_bfrag + (size_t)chunk * NBT * 16 * 64;
    for (int t = 0; t < NBT; t++) {
        #pragma unroll
        for (int ss = 0; ss < 2; ss++) {
            const int s = ng * 2 + ss;
            const uint4* fb = fragc + (size_t)(t * 16 + s * 4) * 64 + lane;

            // load all 8 fragment vectors for this subtile (MLP=8)
            uint4 f[8];
            #pragma unroll
            for (int kt = 0; kt < 4; kt++) {
                f[kt * 2]     = __ldg(fb + kt * 64);
                f[kt * 2 + 1] = __ldg(fb + kt * 64 + 32);
            }

            // prefetch NEXT subtile's fragment lines into L1 (covered by
            // this subtile's ~600-cycle compute; zero register cost)
            {
                const int un = t * 2 + ss + 1;
                if (un < 32) {
                    const int tn = un >> 1;
                    const int sn = ng * 2 + (un & 1);
                    const uint4* fbn =
                        fragc + (size_t)(tn * 16 + sn * 4) * 64 + lane;
                    #pragma unroll
                    for (int kt = 0; kt < 4; kt++) {
                        prefetchL1(fbn + kt * 64);
                        prefetchL1(fbn + kt * 64 + 32);
                    }
                }
            }

            float d[2][4][4];
            #pragma unroll
            for (int j = 0; j < 4; j++) {
                float2 bp = *reinterpret_cast<const float2*>(
                    sBias + t * 128 + s * 32 + j * 8 + tidg * 2);
                #pragma unroll
                for (int mb = 0; mb < 2; mb++) {
                    d[mb][j][0] = bp.x; d[mb][j][1] = bp.y;
                    d[mb][j][2] = bp.x; d[mb][j][3] = bp.y;
                }
            }
            #pragma unroll
            for (int kt = 0; kt < 4; kt++) {
                const uint4 u1 = f[kt * 2], u2 = f[kt * 2 + 1];
                #pragma unroll
                for (int mb = 0; mb < 2; mb++) {
                    mma16816(d[mb][0], aF[mb][kt], u1.x, u1.z);   // n  0- 7
                    mma16816(d[mb][1], aF[mb][kt], u1.y, u1.w);   // n  8-15
                    mma16816(d[mb][2], aF[mb][kt], u2.x, u2.z);   // n 16-23
                    mma16816(d[mb][3], aF[mb][kt], u2.y, u2.w);   // n 24-31
                }
            }
            // per-score top-2 update + subtile max
            const int nb0 = t * 128 + s * 32 + tidg * 2;
            #pragma unroll
            for (int mb = 0; mb < 2; mb++) {
                #pragma unroll
                for (int j = 0; j < 4; j++) {
                    const int n0 = nb0 + j * 8;
                    upd2(t1v[mb*2],   t1i[mb*2],   t2v[mb*2],   d[mb][j][0], n0);
                    upd2(t1v[mb*2],   t1i[mb*2],   t2v[mb*2],   d[mb][j][1], n0+1);
                    upd2(t1v[mb*2+1], t1i[mb*2+1], t2v[mb*2+1], d[mb][j][2], n0);
                    upd2(t1v[mb*2+1], t1i[mb*2+1], t2v[mb*2+1], d[mb][j][3], n0+1);
                }
                float r0m = fmaxf(fmaxf(d[mb][0][0], d[mb][0][1]),
                                  fmaxf(d[mb][1][0], d[mb][1][1]));
                r0m = fmaxf(r0m, fmaxf(fmaxf(d[mb][2][0], d[mb][2][1]),
                                       fmaxf(d[mb][3][0], d[mb][3][1])));
                float r1m = fmaxf(fmaxf(d[mb][0][2], d[mb][0][3]),
                                  fmaxf(d[mb][1][2], d[mb][1][3]));
                r1m = fmaxf(r1m, fmaxf(fmaxf(d[mb][2][2], d[mb][2][3]),
                                       fmaxf(d[mb][3][2], d[mb][3][3])));
                r0m = fmaxf(r0m, __shfl_xor_sync(0xffffffffu, r0m, 1));
                r0m = fmaxf(r0m, __shfl_xor_sync(0xffffffffu, r0m, 2));
                r1m = fmaxf(r1m, __shfl_xor_sync(0xffffffffu, r1m, 1));
                r1m = fmaxf(r1m, __shfl_xor_sync(0xffffffffu, r1m, 2));
                if (tidg == 0) {
                    const int sg  = t * 4 + s;
                    const int row = mg * 32 + mb * 16 + gid;
                    sMax[sg * 128 + row]     = r0m;
                    sMax[sg * 128 + row + 8] = r1m;
                }
            }
        }
    }

    // ---- cross-lane/warp top-2 merge ----
    uint32_t* wl    = reinterpret_cast<uint32_t*>(sm + SM_WL);
    ull*      sBest = reinterpret_cast<ull*>(sm + SM_BEST);
    uint32_t* wcnt  = reinterpret_cast<uint32_t*>(sm + SM_WCNT);
    if (tid == 0) *wcnt = 0;

    #pragma unroll
    for (int sl = 0; sl < 4; sl++) {
        float av = t1v[sl], a2 = t2v[sl]; int ai = t1i[sl];
        #pragma unroll
        for (int off = 1; off <= 2; off <<= 1) {
            float bv = __shfl_xor_sync(0xffffffffu, av, off);
            int   bi = __shfl_xor_sync(0xffffffffu, ai, off);
            float b2 = __shfl_xor_sync(0xffffffffu, a2, off);
            if (bv > av) { a2 = fmaxf(av, b2); av = bv; ai = bi; }
            else         { a2 = fmaxf(a2, bv); }
        }
        if (tidg == 0) {
            const int row = mg * 32 + (sl >> 1) * 16 + gid + (sl & 1) * 8;
            sT1[ng * 128 + row] = av;
            sT2[ng * 128 + row] = a2;
            sTI[ng * 128 + row] = ai;
        }
    }
    __syncthreads();

    // ---- classify tokens: proven winner vs ambiguous (needs exact rescue) ----
    if (tid < 128) {
        float av = sT1[tid],       a2 = sT2[tid];       int ai = sTI[tid];
        float bv = sT1[128 + tid], b2 = sT2[128 + tid]; int bi = sTI[128 + tid];
        float gt1, gt2; int gti;
        if (bv > av) { gt1 = bv; gti = bi; gt2 = fmaxf(av, b2); }
        else         { gt1 = av; gti = ai; gt2 = fmaxf(a2, bv); }
        const float thr2 = sEps[tid];
        if (gt1 - gt2 > thr2) {
            sBest[tid] = (ull)(uint32_t)gti;      // proven exact winner
        } else {
            sBest[tid] = ~0ull;
            const float cth = gt1 - thr2;
            for (int s2 = 0; s2 < 64; s2++)
                if (sMax[s2 * 128 + tid] >= cth) {
                    uint32_t p = atomicAdd(wcnt, 1u);
                    wl[p] = ((uint32_t)tid << 8) | (uint32_t)s2;
                }
        }
    }
    __syncthreads();

    // ---- exact fp32 rescue (rare; R1-identical arithmetic) ----
    const int cnt = *wcnt;
    const float* cqc = g_cbsq + chunk * NCW;
    for (int it = w; it < cnt; it += 8) {
        const uint32_t item = wl[it];
        const int tk = item >> 8, st = item & 255;
        const int n = st * 32 + lane;
        const float4* cp = reinterpret_cast<const float4*>(cbc + (size_t)n * SUB);
        const float4* xv = reinterpret_cast<const float4*>(
            x + (size_t)(t0 + tk) * DIM + chunk * SUB);
        float acc = 0.f;
        #pragma unroll
        for (int q = 0; q < 16; q++) {
            float4 c4 = __ldg(cp + q);
            float4 x4 = xv[q];
            acc = fmaf(c4.x, x4.x, acc);
            acc = fmaf(c4.y, x4.y, acc);
            acc = fmaf(c4.z, x4.z, acc);
            acc = fmaf(c4.w, x4.w, acc);
        }
        const float d2 = fmaf(-2.f, acc, sXsq[tk]) + __ldg(&cqc[n]);
        const ull key = ((ull)ord_f32(d2) << 32) | (uint32_t)n;
        atomicMin(&sBest[tk], key);
    }
    __syncthreads();

    // ---- gather winning codewords ----
    {
        const int r = tid >> 1, h = tid & 1;
        const uint32_t n = (uint32_t)(sBest[r] & 0xFFFFFFFFull);
        const float4* src = reinterpret_cast<const float4*>(
            cbc + (size_t)n * SUB + h * 32);
        float4* dst = reinterpret_cast<float4*>(
            out + (size_t)(t0 + r) * DIM + chunk * SUB + h * 32);
        #pragma unroll
        for (int q = 0; q < 8; q++) dst[q] = src[q];
    }
}

extern "C" void kernel_launch(void* const* d_in, const int* in_sizes, int n_in,
                              void* d_out, int out_size) {
    (void)n_in; (void)out_size;
    const float* x  = (const float*)d_in[0];   // (4,2048,1024) fp32
    const float* cb = (const float*)d_in[1];   // (16,2048,64) fp32
    float* out = (float*)d_out;
    const int tokens = in_sizes[0] / DIM;      // 8192

    cudaFuncSetAttribute(vq_kernel,
                         cudaFuncAttributeMaxDynamicSharedMemorySize, SM_TOTAL);

    prep_kernel<<<C_CHUNKS * NBT, 256, 18432>>>(cb);
    dim3 grid(tokens / TM, C_CHUNKS);
    vq_kernel<<<grid, 256, SM_TOTAL>>>(x, cb, out);
}

// round 12
// speedup vs baseline: 1.5655x; 1.4366x over previous
#include <cuda_runtime.h>
#include <cuda_fp16.h>
#include <stdint.h>

#define C_CHUNKS 16
#define NCW      2048
#define SUB      64
#define DIM      1024
#define TM       128
#define BT       128            // codewords per B tile
#define NBT      (NCW / BT)     // 16

// smem layout (bytes) -- exactly 64KB so 2 CTAs leave ~100KB L1D for B stream
#define SM_A     0              // 128 x 144B = 18432 (A staging for ldmatrix)
#define SM_BIAS  18432          // 2048 f32 = 8192 (all tiles' biases)
#define SM_XSQ   26624          // 128 f32
#define SM_EPS   27136          // 128 f32 (per-token 2*eps threshold)
#define SM_MAX   27648          // 64 x 128 f32 = 32768
#define SM_TOP   60416          // 3 x 256 f32 = 3072
#define SM_BM    63488          // 128 x 2 u32 candidate bitmaps = 1024
#define SM_BEST  64512          // 128 x u64 = 1024
#define SM_TOTAL 65536

typedef unsigned long long ull;

__device__ float    g_cbsq[C_CHUNKS * NCW];
__device__ float    g_bias[C_CHUNKS * NCW];
__device__ unsigned g_cbsqmax[C_CHUNKS];       // per-chunk max |c|^2 (f32 bits)
// B in MMA *fragment order*: [(chunk*16+t)*16 + s*4 + kt] blocks of 64 uint4:
//   [lane]      = {b0,b1,b2,b3}  (n 0-15 of subtile)
//   [32 + lane] = {b4,b5,b6,b7}  (n 16-31 of subtile)
__device__ uint4 g_bfrag[C_CHUNKS * NBT * 16 * 64];

// ---------------------------------------------------------------------------
__device__ __forceinline__ uint32_t smem_u32(const void* p) {
    uint32_t a;
    asm("{ .reg .u64 t; cvta.to.shared.u64 t, %1; cvt.u32.u64 %0, t; }"
        : "=r"(a) : "l"(p));
    return a;
}
__device__ __forceinline__ void ldsm4(uint32_t& r0, uint32_t& r1, uint32_t& r2,
                                      uint32_t& r3, uint32_t a) {
    asm volatile("ldmatrix.sync.aligned.m8n8.x4.shared.b16 {%0,%1,%2,%3}, [%4];"
                 : "=r"(r0), "=r"(r1), "=r"(r2), "=r"(r3) : "r"(a));
}
__device__ __forceinline__ void mma16816(float* d, const uint32_t* a,
                                         uint32_t b0, uint32_t b1) {
    asm volatile(
        "mma.sync.aligned.m16n8k16.row.col.f32.f16.f16.f32 "
        "{%0,%1,%2,%3}, {%4,%5,%6,%7}, {%8,%9}, {%0,%1,%2,%3};"
        : "+f"(d[0]), "+f"(d[1]), "+f"(d[2]), "+f"(d[3])
        : "r"(a[0]), "r"(a[1]), "r"(a[2]), "r"(a[3]), "r"(b0), "r"(b1));
}
__device__ __forceinline__ uint32_t ord_f32(float f) {
    uint32_t u = __float_as_uint(f);
    return (u & 0x80000000u) ? ~u : (u | 0x80000000u);
}
// top-2 update: fmin/fmax form (fma pipe) + predicated index (alu pipe)
__device__ __forceinline__ void upd2(float& t1, int& ti, float& t2,
                                     float v, int n) {
    const bool g = v > t1;
    const float tmin = fminf(v, t1);
    t1 = fmaxf(t1, v);
    t2 = fmaxf(t2, tmin);
    ti = g ? n : ti;
}

// ---------------------------------------------------------------------------
// prep: per (chunk, tile) block: fp16-convert codewords into an LDSM-layout
// smem stage, ldmatrix ONCE, dump warp registers to g_bfrag (bit-identical
// fragments to the mainloop's). Emits cbsq + bias + per-chunk max cbsq
// (warp-reduced + atomicMax; idempotent => graph-replay deterministic).
// grid 256 (chunk*16+t), 256 threads.
// ---------------------------------------------------------------------------
__global__ void prep_kernel(const float* __restrict__ cb) {
    extern __shared__ char sm[];
    const uint32_t smb = smem_u32(sm);
    const int tid = threadIdx.x, w = tid >> 5, lane = tid & 31;
    const int chunk = blockIdx.x >> 4, t = blockIdx.x & 15;

    // stage: row n (128 cw) x 64 k as fp16, 144B row stride
    {
        const int r = tid >> 1, h = tid & 1;
        const int n = chunk * NCW + t * BT + r;
        const float4* cp = reinterpret_cast<const float4*>(
            cb + (size_t)n * SUB + h * 32);
        __half* row = reinterpret_cast<__half*>(sm + r * 144 + h * 64);
        float ssq = 0.f;
        #pragma unroll
        for (int q = 0; q < 8; q++) {
            float4 v = cp[q];
            __half2* dh = reinterpret_cast<__half2*>(row + q * 4);
            dh[0] = __floats2half2_rn(v.x, v.y);
            dh[1] = __floats2half2_rn(v.z, v.w);
            ssq = fmaf(v.x, v.x, ssq); ssq = fmaf(v.y, v.y, ssq);
            ssq = fmaf(v.z, v.z, ssq); ssq = fmaf(v.w, v.w, ssq);
        }
        ssq += __shfl_xor_sync(0xffffffffu, ssq, 1);
        if (h == 0) {
            g_cbsq[n] = ssq;
            g_bias[n] = -0.5f * ssq;
        }
        // warp-reduce max cbsq (all lanes hold pair-complete ssq)
        float m = ssq;
        #pragma unroll
        for (int o = 16; o > 1; o >>= 1)
            m = fmaxf(m, __shfl_xor_sync(0xffffffffu, m, o));
        if (lane == 0)
            atomicMax(&g_cbsqmax[chunk], __float_as_uint(m));
    }
    __syncthreads();

    // warp w: subtile s = w>>1, kt pair = (w&1)*2
    {
        const int s = w >> 1;
        const int bRow = ((lane >> 3) & 1) * 8 + (lane & 7);
        const uint32_t laneOff = bRow * 144 + (lane >> 4) * 16;
        #pragma unroll
        for (int ktl = 0; ktl < 2; ktl++) {
            const int kt = (w & 1) * 2 + ktl;
            uint32_t b0, b1, b2, b3, b4, b5, b6, b7;
            uint32_t ad = smb + s * (32 * 144) + kt * 32 + laneOff;
            ldsm4(b0, b1, b2, b3, ad);
            ldsm4(b4, b5, b6, b7, ad + 16 * 144);
            uint4* dst = g_bfrag + ((size_t)(blockIdx.x * 16 + s * 4 + kt)) * 64;
            dst[lane]      = make_uint4(b0, b1, b2, b3);
            dst[32 + lane] = make_uint4(b4, b5, b6, b7);
        }
    }
}

// ---------------------------------------------------------------------------
// main: HMMA filter with B fragments LDG'd straight to registers (no smem B,
// NO barriers in the mainloop), per-token top-2 gap proof (Cauchy-Schwarz
// error bound), bitmap-driven exact rescue.
// grid (64, 16), 256 threads. Warp w: M-group (w&3)*32, N-half (w>>2).
// ---------------------------------------------------------------------------
__global__ __launch_bounds__(256, 2)
void vq_kernel(const float* __restrict__ x, const float* __restrict__ cb,
               float* __restrict__ out) {
    extern __shared__ char sm[];
    const uint32_t smb = smem_u32(sm);
    const int tid = threadIdx.x, w = tid >> 5, lane = tid & 31;
    const int chunk = blockIdx.y;
    const int t0 = blockIdx.x * TM;
    const float* cbc = cb + (size_t)chunk * NCW * SUB;

    float* sBias = reinterpret_cast<float*>(sm + SM_BIAS);   // 2048 floats
    float* sXsq  = reinterpret_cast<float*>(sm + SM_XSQ);
    float* sEps  = reinterpret_cast<float*>(sm + SM_EPS);
    float* sMax  = reinterpret_cast<float*>(sm + SM_MAX);
    float* sT1   = reinterpret_cast<float*>(sm + SM_TOP);            // [2][128]
    float* sT2   = reinterpret_cast<float*>(sm + SM_TOP + 1024);     // [2][128]
    int*   sTI   = reinterpret_cast<int*>  (sm + SM_TOP + 2048);     // [2][128]
    uint32_t* sBM = reinterpret_cast<uint32_t*>(sm + SM_BM);         // [128][2]
    ull*   sBest = reinterpret_cast<ull*>(sm + SM_BEST);             // [128]

    const float cbmax = __uint_as_float(g_cbsqmax[chunk]);

    // ---- build fp16 A tile + exact xsq + per-token error threshold ----
    {
        const int r = tid >> 1, h = tid & 1;
        const float4* xp = reinterpret_cast<const float4*>(
            x + (size_t)(t0 + r) * DIM + chunk * SUB + h * 32);
        __half* arow = reinterpret_cast<__half*>(sm + SM_A + r * 144 + h * 64);
        float ssq = 0.f;
        #pragma unroll
        for (int q = 0; q < 8; q++) {
            float4 v = xp[q];
            __half2* dh = reinterpret_cast<__half2*>(arow + q * 4);
            dh[0] = __floats2half2_rn(v.x, v.y);
            dh[1] = __floats2half2_rn(v.z, v.w);
            ssq = fmaf(v.x, v.x, ssq); ssq = fmaf(v.y, v.y, ssq);
            ssq = fmaf(v.z, v.z, ssq); ssq = fmaf(v.w, v.w, ssq);
        }
        ssq += __shfl_xor_sync(0xffffffffu, ssq, 1);
        if (h == 0) {
            sXsq[r] = ssq;
            // 2*eps: Cauchy-Schwarz fp16-rounding bound |err| <= 2^-10*|x||c|
            // (1.03e-3 >= 2^-10 incl 2nd order) + 4e-3 fp32-accum/bias slack
            sEps[r] = 2.f * (1.03e-3f * sqrtf(ssq * cbmax) + 4e-3f);
        }
    }
    // ---- preload ALL tile biases once (2048 f32) ----
    #pragma unroll
    for (int i = 0; i < 8; i++)
        sBias[i * 256 + tid] = g_bias[chunk * NCW + i * 256 + tid];
    __syncthreads();

    const int mg = w & 3;    // M group: token rows [mg*32, mg*32+32)
    const int ng = w >> 2;   // N half: subtiles s = 2*ng, 2*ng+1

    // ---- A fragments: 2 m16 blocks, registers for the whole kernel ----
    uint32_t aF[2][4][4];
    {
        const int aRow = ((lane >> 3) & 1) * 8 + (lane & 7);
        const int aK8  = lane >> 4;
        #pragma unroll
        for (int mb = 0; mb < 2; mb++) {
            uint32_t abase = smb + SM_A + (mg * 32 + mb * 16 + aRow) * 144
                           + aK8 * 16;
            #pragma unroll
            for (int kt = 0; kt < 4; kt++)
                ldsm4(aF[mb][kt][0], aF[mb][kt][1], aF[mb][kt][2],
                      aF[mb][kt][3], abase + kt * 32);
        }
    }

    const int gid = lane >> 2, tidg = lane & 3;

    // per-lane top-2 trackers; slot = mb*2 + half (half1 = row+8)
    float t1v[4], t2v[4]; int t1i[4];
    #pragma unroll
    for (int i = 0; i < 4; i++) {
        t1v[i] = -3.4028235e38f; t2v[i] = -3.4028235e38f; t1i[i] = 0;
    }

    // ---- mainloop: 16 tiles x 2 subtiles, ZERO barriers ----
    const uint4* fragc = g_bfrag + (size_t)chunk * NBT * 16 * 64;
    for (int t = 0; t < NBT; t++) {
        #pragma unroll
        for (int ss = 0; ss < 2; ss++) {
            const int s = ng * 2 + ss;
            const uint4* fb = fragc + (size_t)(t * 16 + s * 4) * 64 + lane;

            // load all 8 fragment vectors for this subtile (MLP=8)
            uint4 f[8];
            #pragma unroll
            for (int kt = 0; kt < 4; kt++) {
                f[kt * 2]     = __ldg(fb + kt * 64);
                f[kt * 2 + 1] = __ldg(fb + kt * 64 + 32);
            }

            float d[2][4][4];
            #pragma unroll
            for (int j = 0; j < 4; j++) {
                float2 bp = *reinterpret_cast<const float2*>(
                    sBias + t * 128 + s * 32 + j * 8 + tidg * 2);
                #pragma unroll
                for (int mb = 0; mb < 2; mb++) {
                    d[mb][j][0] = bp.x; d[mb][j][1] = bp.y;
                    d[mb][j][2] = bp.x; d[mb][j][3] = bp.y;
                }
            }
            #pragma unroll
            for (int kt = 0; kt < 4; kt++) {
                const uint4 u1 = f[kt * 2], u2 = f[kt * 2 + 1];
                #pragma unroll
                for (int mb = 0; mb < 2; mb++) {
                    mma16816(d[mb][0], aF[mb][kt], u1.x, u1.z);   // n  0- 7
                    mma16816(d[mb][1], aF[mb][kt], u1.y, u1.w);   // n  8-15
                    mma16816(d[mb][2], aF[mb][kt], u2.x, u2.z);   // n 16-23
                    mma16816(d[mb][3], aF[mb][kt], u2.y, u2.w);   // n 24-31
                }
            }
            // per-score top-2 update + subtile max
            const int nb0 = t * 128 + s * 32 + tidg * 2;
            #pragma unroll
            for (int mb = 0; mb < 2; mb++) {
                #pragma unroll
                for (int j = 0; j < 4; j++) {
                    const int n0 = nb0 + j * 8;
                    upd2(t1v[mb*2],   t1i[mb*2],   t2v[mb*2],   d[mb][j][0], n0);
                    upd2(t1v[mb*2],   t1i[mb*2],   t2v[mb*2],   d[mb][j][1], n0+1);
                    upd2(t1v[mb*2+1], t1i[mb*2+1], t2v[mb*2+1], d[mb][j][2], n0);
                    upd2(t1v[mb*2+1], t1i[mb*2+1], t2v[mb*2+1], d[mb][j][3], n0+1);
                }
                float r0m = fmaxf(fmaxf(d[mb][0][0], d[mb][0][1]),
                                  fmaxf(d[mb][1][0], d[mb][1][1]));
                r0m = fmaxf(r0m, fmaxf(fmaxf(d[mb][2][0], d[mb][2][1]),
                                       fmaxf(d[mb][3][0], d[mb][3][1])));
                float r1m = fmaxf(fmaxf(d[mb][0][2], d[mb][0][3]),
                                  fmaxf(d[mb][1][2], d[mb][1][3]));
                r1m = fmaxf(r1m, fmaxf(fmaxf(d[mb][2][2], d[mb][2][3]),
                                       fmaxf(d[mb][3][2], d[mb][3][3])));
                r0m = fmaxf(r0m, __shfl_xor_sync(0xffffffffu, r0m, 1));
                r0m = fmaxf(r0m, __shfl_xor_sync(0xffffffffu, r0m, 2));
                r1m = fmaxf(r1m, __shfl_xor_sync(0xffffffffu, r1m, 1));
                r1m = fmaxf(r1m, __shfl_xor_sync(0xffffffffu, r1m, 2));
                if (tidg == 0) {
                    const int sg  = t * 4 + s;
                    const int row = mg * 32 + mb * 16 + gid;
                    sMax[sg * 128 + row]     = r0m;
                    sMax[sg * 128 + row + 8] = r1m;
                }
            }
        }
    }

    // ---- cross-lane/warp top-2 merge ----
    #pragma unroll
    for (int sl = 0; sl < 4; sl++) {
        float av = t1v[sl], a2 = t2v[sl]; int ai = t1i[sl];
        #pragma unroll
        for (int off = 1; off <= 2; off <<= 1) {
            float bv = __shfl_xor_sync(0xffffffffu, av, off);
            int   bi = __shfl_xor_sync(0xffffffffu, ai, off);
            float b2 = __shfl_xor_sync(0xffffffffu, a2, off);
            if (bv > av) { a2 = fmaxf(av, b2); av = bv; ai = bi; }
            else         { a2 = fmaxf(a2, bv); }
        }
        if (tidg == 0) {
            const int row = mg * 32 + (sl >> 1) * 16 + gid + (sl & 1) * 8;
            sT1[ng * 128 + row] = av;
            sT2[ng * 128 + row] = a2;
            sTI[ng * 128 + row] = ai;
        }
    }
    __syncthreads();

    // ---- classify: proven winner vs ambiguous (candidate bitmap) ----
    if (tid < 128) {
        float av = sT1[tid],       a2 = sT2[tid];       int ai = sTI[tid];
        float bv = sT1[128 + tid], b2 = sT2[128 + tid]; int bi = sTI[128 + tid];
        float gt1, gt2; int gti;
        if (bv > av) { gt1 = bv; gti = bi; gt2 = fmaxf(av, b2); }
        else         { gt1 = av; gti = ai; gt2 = fmaxf(a2, bv); }
        const float thr2 = sEps[tid];
        uint32_t m0 = 0, m1 = 0;
        if (gt1 - gt2 > thr2) {
            sBest[tid] = (ull)(uint32_t)gti;      // proven exact winner
        } else {
            const float cth = gt1 - thr2;
            #pragma unroll 8
            for (int s2 = 0; s2 < 32; s2++)
                if (sMax[s2 * 128 + tid] >= cth) m0 |= (1u << s2);
            #pragma unroll 8
            for (int s2 = 0; s2 < 32; s2++)
                if (sMax[(s2 + 32) * 128 + tid] >= cth) m1 |= (1u << s2);
        }
        sBM[tid * 2]     = m0;
        sBM[tid * 2 + 1] = m1;
    }
    __syncthreads();

    // ---- exact fp32 rescue (bitmap-driven; R1-identical arithmetic) ----
    const float* cqc = g_cbsq + chunk * NCW;
    #pragma unroll 1
    for (int i = 0; i < 16; i++) {
        const int tk = w * 16 + i;
        ull mm = ((ull)sBM[tk * 2 + 1] << 32) | (ull)sBM[tk * 2];
        if (mm == 0) continue;
        const float xsq_tk = sXsq[tk];
        const float4* xv = reinterpret_cast<const float4*>(
            x + (size_t)(t0 + tk) * DIM + chunk * SUB);
        ull best = ~0ull;
        while (mm) {
            const int s2 = __ffsll(mm) - 1;
            mm &= mm - 1;
            const int n = s2 * 32 + lane;
            const float4* cp = reinterpret_cast<const float4*>(
                cbc + (size_t)n * SUB);
            float acc = 0.f;
            #pragma unroll
            for (int q = 0; q < 16; q++) {
                float4 c4 = __ldg(cp + q);
                float4 x4 = xv[q];
                acc = fmaf(c4.x, x4.x, acc);
                acc = fmaf(c4.y, x4.y, acc);
                acc = fmaf(c4.z, x4.z, acc);
                acc = fmaf(c4.w, x4.w, acc);
            }
            const float d2 = fmaf(-2.f, acc, xsq_tk) + __ldg(&cqc[n]);
            const ull key = ((ull)ord_f32(d2) << 32) | (uint32_t)n;
            if (key < best) best = key;
        }
        #pragma unroll
        for (int off = 16; off > 0; off >>= 1) {
            ull o = __shfl_xor_sync(0xffffffffu, best, off);
            if (o < best) best = o;
        }
        if (lane == 0) sBest[tk] = best;
    }
    __syncthreads();

    // ---- gather winning codewords ----
    {
        const int r = tid >> 1, h = tid & 1;
        const uint32_t n = (uint32_t)(sBest[r] & 0xFFFFFFFFull);
        const float4* src = reinterpret_cast<const float4*>(
            cbc + (size_t)n * SUB + h * 32);
        float4* dst = reinterpret_cast<float4*>(
            out + (size_t)(t0 + r) * DIM + chunk * SUB + h * 32);
        #pragma unroll
        for (int q = 0; q < 8; q++) dst[q] = src[q];
    }
}

extern "C" void kernel_launch(void* const* d_in, const int* in_sizes, int n_in,
                              void* d_out, int out_size) {
    (void)n_in; (void)out_size;
    const float* x  = (const float*)d_in[0];   // (4,2048,1024) fp32
    const float* cb = (const float*)d_in[1];   // (16,2048,64) fp32
    float* out = (float*)d_out;
    const int tokens = in_sizes[0] / DIM;      // 8192

    cudaFuncSetAttribute(vq_kernel,
                         cudaFuncAttributeMaxDynamicSharedMemorySize, SM_TOTAL);

    prep_kernel<<<C_CHUNKS * NBT, 256, 18432>>>(cb);
    dim3 grid(tokens / TM, C_CHUNKS);
    vq_kernel<<<grid, 256, SM_TOTAL>>>(x, cb, out);
}